// round 17
// baseline (speedup 1.0000x reference)
#include <cuda_runtime.h>

#define NQ      12
#define NT      512         // threads per CTA (16 warps)
#define NR      8           // amplitudes per thread PER SAMPLE (2 samples interleaved)
#define NLAYERS 4
#define XP      9           // padded row pitch (ulonglong2 elements), rows of 8
#define XSZ     (512 * XP)  // ulonglong2 elements per exchange buffer
#define PHYS(n) ((n) + ((n) >> 3))   // (n>>3)*XP + (n&7)

typedef unsigned long long u64;

// ---- packed f32x2 helpers (re in lo 32 bits, im in hi 32 bits) ----
__device__ __forceinline__ u64 pack2(float lo, float hi) {
    u64 r; asm("mov.b64 %0, {%1, %2};" : "=l"(r) : "f"(lo), "f"(hi)); return r;
}
__device__ __forceinline__ void unpack2(u64 v, float& lo, float& hi) {
    asm("mov.b64 {%0, %1}, %2;" : "=f"(lo), "=f"(hi) : "l"(v));
}
__device__ __forceinline__ u64 swap2(u64 v) {
    u64 r;
    asm("{\n\t.reg .b32 l, h;\n\tmov.b64 {l, h}, %1;\n\tmov.b64 %0, {h, l};\n\t}"
        : "=l"(r) : "l"(v));
    return r;
}
__device__ __forceinline__ u64 ffma2(u64 a, u64 b, u64 c) {
    u64 r; asm("fma.rn.f32x2 %0, %1, %2, %3;" : "=l"(r) : "l"(a), "l"(b), "l"(c)); return r;
}
__device__ __forceinline__ u64 fmul2(u64 a, u64 b) {
    u64 r; asm("mul.rn.f32x2 %0, %1, %2;" : "=l"(r) : "l"(a), "l"(b)); return r;
}
__device__ __forceinline__ u64 add2(u64 a, u64 b) {
    u64 r; asm("add.rn.f32x2 %0, %1, %2;" : "=l"(r) : "l"(a), "l"(b)); return r;
}
__device__ __forceinline__ u64 neg2(u64 v) { return v ^ 0x8000000080000000ULL; }
__device__ __forceinline__ float2 cmul(float2 a, float2 b) {
    return make_float2(fmaf(-a.y, b.y, a.x * b.x), fmaf(a.y, b.x, a.x * b.y));
}

// State element: .x = sample-a amp (re,im packed), .y = sample-b amp.

// ---- REAL RY gate on register bit P (0..2), both samples (shared coeffs) ----
template<int P>
__device__ __forceinline__ void gate_ry2(ulonglong2* st, const u64* g) {
    ulonglong2 cs = *(const ulonglong2*)(g);   // C, S
    u64 NS = g[2];
#pragma unroll
    for (int k = 0; k < NR / 2; k++) {
        const int r0 = ((k >> P) << (P + 1)) | (k & ((1 << P) - 1));
        const int r1 = r0 | (1 << P);
        ulonglong2 m0 = st[r0], m1 = st[r1];
        st[r0].x = ffma2(NS,   m1.x, fmul2(cs.x, m0.x));
        st[r0].y = ffma2(NS,   m1.y, fmul2(cs.x, m0.y));
        st[r1].x = ffma2(cs.x, m1.x, fmul2(cs.y, m0.x));
        st[r1].y = ffma2(cs.x, m1.y, fmul2(cs.y, m0.y));
    }
}

// ======================= layouts (R14 schedule, 16B elements) =======================
// amp index n[11:0], wire q <-> bit (11-q). phys(n) = n + (n>>3). thread bits t8..t0.
// Layout A: n = (t<<3)|r                      reg = n[2:0]  (wires 9,10,11)
// Layout B: n = ((t>>3)<<6)|(r<<3)|(t&7)      reg = n[5:3]  (wires 6,7,8)
// Layout C: n = ((t>>6)<<9)|(r<<6)|(t&63)     reg = n[8:6]  (wires 3,4,5)
// Layout D: n = (r<<9)|t                      reg = n[11:9] (wires 0,1,2)
// A<->B warp-local. B<->C, C<->D cross-warp. CTA round-trips alternate x0/x1,
// one __syncthreads each. 16B elements conflict-free (index mod 8 distinct per
// quarter-warp in all four layouts).

#define ADDR_A(t, r) ((t) * XP + (r))
#define ADDR_B(t, r) (((((t) >> 3) << 3) | (r)) * XP + ((t) & 7))
#define ADDR_C(t, r) (((((t) >> 6) << 6) | ((r) << 3) | (((t) >> 3) & 7)) * XP + ((t) & 7))
#define ADDR_D(t, r) (((((r) << 6) | ((t) >> 3))) * XP + ((t) & 7))

__device__ __forceinline__ void exch_A_to_B(ulonglong2* st, int t, ulonglong2* x) { // WL
#pragma unroll
    for (int r = 0; r < NR; r++) x[ADDR_A(t, r)] = st[r];
    __syncwarp();
#pragma unroll
    for (int r = 0; r < NR; r++) st[r] = x[ADDR_B(t, r)];
    __syncwarp();
}
__device__ __forceinline__ void exch_B_to_A(ulonglong2* st, int t, ulonglong2* x) { // WL
#pragma unroll
    for (int r = 0; r < NR; r++) x[ADDR_B(t, r)] = st[r];
    __syncwarp();
#pragma unroll
    for (int r = 0; r < NR; r++) st[r] = x[ADDR_A(t, r)];
    __syncwarp();
}
__device__ __forceinline__ void exch_B_to_C(ulonglong2* st, int t, ulonglong2* x) { // CTA
#pragma unroll
    for (int r = 0; r < NR; r++) x[ADDR_B(t, r)] = st[r];
    __syncthreads();
#pragma unroll
    for (int r = 0; r < NR; r++) st[r] = x[ADDR_C(t, r)];
}
__device__ __forceinline__ void exch_C_to_B(ulonglong2* st, int t, ulonglong2* x) { // CTA
#pragma unroll
    for (int r = 0; r < NR; r++) x[ADDR_C(t, r)] = st[r];
    __syncthreads();
#pragma unroll
    for (int r = 0; r < NR; r++) st[r] = x[ADDR_B(t, r)];
    __syncwarp();   // reads own rows; order before this warp's next WL write
}
__device__ __forceinline__ void exch_C_to_D(ulonglong2* st, int t, ulonglong2* x) { // CTA
#pragma unroll
    for (int r = 0; r < NR; r++) x[ADDR_C(t, r)] = st[r];
    __syncthreads();
#pragma unroll
    for (int r = 0; r < NR; r++) st[r] = x[ADDR_D(t, r)];
}
__device__ __forceinline__ void exch_D_to_C(ulonglong2* st, int t, ulonglong2* x) { // CTA
#pragma unroll
    for (int r = 0; r < NR; r++) x[ADDR_D(t, r)] = st[r];
    __syncthreads();
#pragma unroll
    for (int r = 0; r < NR; r++) st[r] = x[ADDR_C(t, r)];
}

// ======================= RY-only sweeps (R14 buffer schedule) =======================
__device__ __forceinline__ void sweep_D_to_A(ulonglong2* st, const u64* G, int t,
                                             ulonglong2* x0, ulonglong2* x1) {
    gate_ry2<2>(st, G + 0 * 4);  gate_ry2<1>(st, G + 1 * 4);  gate_ry2<0>(st, G + 2 * 4);
    exch_D_to_C(st, t, x0);
    gate_ry2<2>(st, G + 3 * 4);  gate_ry2<1>(st, G + 4 * 4);  gate_ry2<0>(st, G + 5 * 4);
    exch_C_to_B(st, t, x1);
    gate_ry2<2>(st, G + 6 * 4);  gate_ry2<1>(st, G + 7 * 4);  gate_ry2<0>(st, G + 8 * 4);
    exch_B_to_A(st, t, x1);     // WL on x1: prior x1 reads were own-row-only
    gate_ry2<2>(st, G + 9 * 4);  gate_ry2<1>(st, G + 10 * 4); gate_ry2<0>(st, G + 11 * 4);
}
__device__ __forceinline__ void sweep_A_to_D(ulonglong2* st, const u64* G, int t,
                                             ulonglong2* x0, ulonglong2* x1) {
    gate_ry2<2>(st, G + 9 * 4);  gate_ry2<1>(st, G + 10 * 4); gate_ry2<0>(st, G + 11 * 4);
    exch_A_to_B(st, t, x1);     // WL on x1 (last CTA use of x1 >= 2 bars ago)
    gate_ry2<2>(st, G + 6 * 4);  gate_ry2<1>(st, G + 7 * 4);  gate_ry2<0>(st, G + 8 * 4);
    exch_B_to_C(st, t, x1);
    gate_ry2<2>(st, G + 3 * 4);  gate_ry2<1>(st, G + 4 * 4);  gate_ry2<0>(st, G + 5 * 4);
    exch_C_to_D(st, t, x0);
    gate_ry2<2>(st, G + 0 * 4);  gate_ry2<1>(st, G + 1 * 4);  gate_ry2<0>(st, G + 2 * 4);
}

// ======================= global diagonals (tables built once, both samples) =======================
// Layout A: wires 0..8 = t8..t0, wires 9..11 = r2..r0.
__device__ __forceinline__ void diag_A(ulonglong2* st, int t, const float2 (*P)[2]) {
    float2 p01 = cmul(P[0][(t >> 8) & 1], P[1][(t >> 7) & 1]);
    float2 p23 = cmul(P[2][(t >> 6) & 1], P[3][(t >> 5) & 1]);
    float2 p45 = cmul(P[4][(t >> 4) & 1], P[5][(t >> 3) & 1]);
    float2 p67 = cmul(P[6][(t >> 2) & 1], P[7][(t >> 1) & 1]);
    float2 ph  = cmul(cmul(cmul(p01, p23), cmul(p45, p67)), P[8][t & 1]);
    u64 Ac[8], Bc[8];
    float2 p9A = cmul(ph, P[9][0]), p9B = cmul(ph, P[9][1]);
#pragma unroll
    for (int i = 0; i < 8; i++) {
        float2 e = cmul((i & 4) ? p9B : p9A,
                        cmul(P[10][(i >> 1) & 1], P[11][i & 1]));
        Ac[i] = pack2(e.x, e.x);  Bc[i] = pack2(-e.y, e.y);
    }
#pragma unroll
    for (int r = 0; r < NR; r++) {
        st[r].x = ffma2(Bc[r], swap2(st[r].x), fmul2(Ac[r], st[r].x));
        st[r].y = ffma2(Bc[r], swap2(st[r].y), fmul2(Ac[r], st[r].y));
    }
}
// Layout D: wires 3..11 = t8..t0, wires 0..2 = r2..r0.
__device__ __forceinline__ void diag_D(ulonglong2* st, int t, const float2 (*P)[2]) {
    float2 p01 = cmul(P[3][(t >> 8) & 1], P[4][(t >> 7) & 1]);
    float2 p23 = cmul(P[5][(t >> 6) & 1], P[6][(t >> 5) & 1]);
    float2 p45 = cmul(P[7][(t >> 4) & 1], P[8][(t >> 3) & 1]);
    float2 p67 = cmul(P[9][(t >> 2) & 1], P[10][(t >> 1) & 1]);
    float2 ph  = cmul(cmul(cmul(p01, p23), cmul(p45, p67)), P[11][t & 1]);
    u64 Ac[8], Bc[8];
    float2 p0A = cmul(ph, P[0][0]), p0B = cmul(ph, P[0][1]);
#pragma unroll
    for (int i = 0; i < 8; i++) {
        float2 e = cmul((i & 4) ? p0B : p0A,
                        cmul(P[1][(i >> 1) & 1], P[2][i & 1]));
        Ac[i] = pack2(e.x, e.x);  Bc[i] = pack2(-e.y, e.y);
    }
#pragma unroll
    for (int r = 0; r < NR; r++) {
        st[r].x = ffma2(Bc[r], swap2(st[r].x), fmul2(Ac[r], st[r].x));
        st[r].y = ffma2(Bc[r], swap2(st[r].y), fmul2(Ac[r], st[r].y));
    }
}

// ======================= batched CNOT ring (shared indices, 128-bit data) =======================
// U[i] = image of n-bit-i unit vector under M = T0∘...∘T11 (reverse ring order).
template<bool LAYOUT_A>
__device__ __forceinline__ void cnotx(ulonglong2* st, int t, ulonglong2* x, const unsigned* U) {
    // thread-bit images: LAYOUT_A -> n bits 3..11; LAYOUT_D -> n bits 0..8
    const unsigned* UT = U + (LAYOUT_A ? 3 : 0);
    unsigned v0 = 0;
#pragma unroll
    for (int j = 0; j < 9; j++)
        if (t & (1 << j)) v0 ^= UT[j];
#pragma unroll
    for (int r = 0; r < NR; r++) {
        unsigned n = LAYOUT_A ? (((unsigned)t << 3) | (unsigned)r)
                              : (((unsigned)r << 9) | (unsigned)t);
        x[PHYS(n)] = st[r];
    }
    __syncthreads();
    // reg-bit images: LAYOUT_A -> n bits 0..2; LAYOUT_D -> n bits 9..11
    const unsigned* UR = U + (LAYOUT_A ? 0 : 9);
    unsigned u0 = UR[0], u1 = UR[1], u2 = UR[2];
#pragma unroll
    for (int r = 0; r < NR; r++) {            // r compile-time -> constant-folded XORs
        unsigned m = v0;
        if (r & 4) m ^= u2;
        if (r & 2) m ^= u1;
        if (r & 1) m ^= u0;
        st[r] = x[PHYS(m)];
    }
}

// GF(2) ring transform (reverse order), setup threads only.
__device__ __forceinline__ unsigned ring_map(unsigned v, unsigned mask) {
#pragma unroll
    for (int k = NQ - 1; k >= 0; k--) {
        if (mask & (1u << k)) {
            const int cb = 11 - k;
            const int tb = 11 - ((k + 1) % NQ);
            v ^= ((v >> cb) & 1u) << tb;
        }
    }
    return v;
}

// packed-pair warp reduction: lo and hi halves reduced independently
__device__ __forceinline__ u64 wred2(u64 v) {
#pragma unroll
    for (int o = 16; o; o >>= 1) v = add2(v, __shfl_xor_sync(0xFFFFFFFFu, v, o));
    return v;
}

__global__ void __launch_bounds__(NT)
qsim_kernel(const float* __restrict__ x,       // (B, 12)
            const float* __restrict__ w,       // (4, 12, 3)
            const float* __restrict__ ent,     // (4, 12)
            float* __restrict__ out)           // (B, 12)
{
    extern __shared__ __align__(16) ulonglong2 dsm[];   // 2 exchange buffers
    ulonglong2* x0 = dsm;
    ulonglong2* x1 = dsm + XSZ;

    __shared__ __align__(16) u64 Usm[48 * 4];            // RY coeffs (shared)
    __shared__ float2 Phs1[48][2];                       // RZ(phi) phases
    __shared__ float2 Phs2[48][2];                       // RZ(omega) phases
    __shared__ u64 red[(NT / 32) * NQ];                  // packed pair reductions
    __shared__ float2 encV[2][NQ][2];                    // per-sample encoding amps
    __shared__ unsigned maskbits[NLAYERS];
    __shared__ __align__(16) unsigned units_sm[NLAYERS][16];

    const int b0   = blockIdx.x * 2;
    const int t    = threadIdx.x;
    const int lane = t & 31;
    const int wid  = t >> 5;

    // ---- precompute (weights shared, encoding per sample) ----
    if (t < 128) {
        const float PI = 3.14159265358979323846f;
        if (t < 2 * NQ) {
            int s = t / NQ, q = t % NQ;
            float xv = __ldg(&x[(b0 + s) * NQ + q]);
            float sn, c;  sincosf(0.5f * PI * xv, &sn, &c);
            float sh, ch; sincosf(0.5f * PI * xv * xv, &sh, &ch);
            float2 a0 = make_float2( c * ch, -c * sh);
            float2 a1 = make_float2( sn * ch,  sn * sh);
            float pf = __ldg(&w[q * 3 + 0]);          // layer 0 phi
            float sp, cp; sincosf(0.5f * pf, &sp, &cp);
            encV[s][q][0] = cmul(a0, make_float2(cp, -sp));
            encV[s][q][1] = cmul(a1, make_float2(cp,  sp));
        } else if (t < 24 + 48) {
            int gi = t - 24;   // 0..47
            float phi = __ldg(&w[gi * 3 + 0]);
            float th  = __ldg(&w[gi * 3 + 1]);
            float om  = __ldg(&w[gi * 3 + 2]);
            float sn, c;  sincosf(0.5f * th, &sn, &c);
            u64* g = &Usm[gi * 4];
            g[0] = pack2(c, c);  g[1] = pack2(sn, sn);  g[2] = pack2(-sn, -sn);
            float sp, cp; sincosf(0.5f * phi, &sp, &cp);
            Phs1[gi][0] = make_float2(cp, -sp);
            Phs1[gi][1] = make_float2(cp,  sp);
            float so, co; sincosf(0.5f * om, &so, &co);
            Phs2[gi][0] = make_float2(co, -so);
            Phs2[gi][1] = make_float2(co,  so);
        } else if (t < 76) {
            int l = t - 72;
            unsigned mm = 0;
#pragma unroll
            for (int i = 0; i < NQ; i++)
                mm |= (__ldg(&ent[l * NQ + i]) > 0.5f ? 1u : 0u) << i;
            maskbits[l] = mm;
        }
    }
    __syncthreads();

    // ---- ring-perm unit images (threads 128..175); consumed after next CTA bar ----
    if (t >= 128 && t < 128 + NLAYERS * NQ) {
        int idx = t - 128, l = idx / NQ, i = idx % NQ;
        units_sm[l][i] = ring_map(1u << i, maskbits[l]);
    }

    // ---- product-state init for both samples, layout D, interleaved ----
    // n = (r<<9)|t: wires 0..2 = r2..r0, wires 3..11 = t8..t0.
    ulonglong2 st[NR];
#pragma unroll
    for (int s = 0; s < 2; s++) {
        const float2 (*eV)[2] = encV[s];
        float2 q34 = cmul(eV[3][(t >> 8) & 1], eV[4][(t >> 7) & 1]);
        float2 q56 = cmul(eV[5][(t >> 6) & 1], eV[6][(t >> 5) & 1]);
        float2 q78 = cmul(eV[7][(t >> 4) & 1], eV[8][(t >> 3) & 1]);
        float2 q9A = cmul(eV[9][(t >> 2) & 1], eV[10][(t >> 1) & 1]);
        float2 cm  = cmul(cmul(cmul(q34, q56), cmul(q78, q9A)), eV[11][t & 1]);
        float2 e0A = cmul(cm, eV[0][0]), e0B = cmul(cm, eV[0][1]);
#pragma unroll
        for (int r = 0; r < NR; r++) {
            float2 a = cmul((r & 4) ? e0B : e0A,
                            cmul(eV[1][(r >> 1) & 1], eV[2][r & 1]));
            if (s == 0) st[r].x = pack2(a.x, a.y);
            else        st[r].y = pack2(a.x, a.y);
        }
    }

    // ---- layers: RY sweep, D2 diag, CNOT perm, D1 diag of next layer ----
    // CTA RT buffer order: L0 [x0,x1,cnot x0] L1 [x1,x0,cnot x1] L2,L3 repeat.
    {
        sweep_D_to_A(st, Usm +  0 * 48, t, x0, x1);
        diag_A(st, t, &Phs2[0]);
        cnotx<true>(st, t, x0, units_sm[0]);
        diag_A(st, t, &Phs1[12]);

        sweep_A_to_D(st, Usm +  1 * 48, t, x0, x1);
        diag_D(st, t, &Phs2[12]);
        cnotx<false>(st, t, x1, units_sm[1]);
        diag_D(st, t, &Phs1[24]);

        sweep_D_to_A(st, Usm +  2 * 48, t, x0, x1);
        diag_A(st, t, &Phs2[24]);
        cnotx<true>(st, t, x0, units_sm[2]);
        diag_A(st, t, &Phs1[36]);

        sweep_A_to_D(st, Usm +  3 * 48, t, x0, x1);
        // D2_3 dropped: |amp|^2 is phase-invariant
        cnotx<false>(st, t, x1, units_sm[3]);
    }

    // ---- readout in layout D, both samples packed (lo=a, hi=b) ----
    // wires 0..2 = r2..r0; wires 3..6 = t8..t5 (wid bits); wires 7..11 = t4..t0 (lane bits)
    float psA = 0.f, a0A = 0.f, a1A = 0.f, a2A = 0.f;
    float psB = 0.f, a0B = 0.f, a1B = 0.f, a2B = 0.f;
#pragma unroll
    for (int r = 0; r < NR; r++) {
        float re, im;
        unpack2(st[r].x, re, im);
        float pa = fmaf(re, re, im * im);
        unpack2(st[r].y, re, im);
        float pb = fmaf(re, re, im * im);
        psA += pa;                      psB += pb;
        a0A += (r & 4) ? -pa : pa;      a0B += (r & 4) ? -pb : pb;
        a1A += (r & 2) ? -pa : pa;      a1B += (r & 2) ? -pb : pb;
        a2A += (r & 1) ? -pa : pa;      a2B += (r & 1) ? -pb : pb;
    }
    u64 ps  = pack2(psA, psB);
    u64 r0  = wred2(pack2(a0A, a0B));
    u64 r1  = wred2(pack2(a1A, a1B));
    u64 r2  = wred2(pack2(a2A, a2B));
    u64 pss = wred2(ps);
    u64 s7  = wred2((lane & 16) ? neg2(ps) : ps);   // wire 7  = t4
    u64 s8  = wred2((lane &  8) ? neg2(ps) : ps);   // wire 8  = t3
    u64 s9  = wred2((lane &  4) ? neg2(ps) : ps);   // wire 9  = t2
    u64 s10 = wred2((lane &  2) ? neg2(ps) : ps);   // wire 10 = t1
    u64 s11 = wred2((lane &  1) ? neg2(ps) : ps);   // wire 11 = t0
    if (lane == 0) {
        u64* rw = &red[wid * NQ];
        rw[0] = r0;  rw[1] = r1;  rw[2] = r2;
        rw[3] = (wid & 8) ? neg2(pss) : pss;   // wire 3 = t8
        rw[4] = (wid & 4) ? neg2(pss) : pss;   // wire 4 = t7
        rw[5] = (wid & 2) ? neg2(pss) : pss;   // wire 5 = t6
        rw[6] = (wid & 1) ? neg2(pss) : pss;   // wire 6 = t5
        rw[7] = s7;  rw[8] = s8;  rw[9] = s9;  rw[10] = s10;  rw[11] = s11;
    }
    __syncthreads();

    if (t < NQ) {
        u64 s = red[t];
#pragma unroll
        for (int wi = 1; wi < NT / 32; wi++) s = add2(s, red[wi * NQ + t]);
        float va, vb; unpack2(s, va, vb);
        out[b0 * NQ + t]       = va;   // SCALE = 1
        out[(b0 + 1) * NQ + t] = vb;
    }
}

extern "C" void kernel_launch(void* const* d_in, const int* in_sizes, int n_in,
                              void* d_out, int out_size)
{
    const float* x   = (const float*)d_in[0];   // (B, 12)
    const float* w   = (const float*)d_in[1];   // (4, 12, 3)
    const float* ent = (const float*)d_in[2];   // (4, 12)
    float* out = (float*)d_out;                 // (B, 12)

    const size_t shmem = 2 * XSZ * sizeof(ulonglong2);  // 147456 B dynamic
    cudaFuncSetAttribute((const void*)qsim_kernel,
                         cudaFuncAttributeMaxDynamicSharedMemorySize, (int)shmem);

    int B = in_sizes[0] / NQ;
    qsim_kernel<<<B / 2, NT, shmem>>>(x, w, ent, out);
}